// round 15
// baseline (speedup 1.0000x reference)
#include <cuda_runtime.h>
#include <math.h>

#define HH 512
#define WW 512
#define CHW 128
#define FHW 256
#define CF 256
#define NCc 3
#define NPTS 2048
#define NUM_OVER 6144
#define CHUNK 6
#define STEP1 1536
#define STEP2 512
#define BB 2
#define FEAT_DIM 259
#define FEAT_PAD 260
#define NROWS (BB*NPTS)
#define FINE_FLAT (BB*NPTS*CF)
#define OUT_OFF (BB*NCc*NPTS)
#define MASK_SIZE (BB*HH*WW)
#define RPB 32                               // rows per MLP block (1 wave: 128 blocks)
#define NPR (RPB/2)                          // 16 row pairs
#define NWORDS (HH*WW/32)
#define W1D_ULL (FEAT_PAD*256)               // 66560 duplicated f32x2 weights
#define W2D_ULL (FEAT_PAD*128)               // 33280
#define UNC_BLOCKS 12
#define REPACK_BLOCKS 98                     // 98*1024 >= 66560+33280

// ---------------- device scratch ----------------
__device__ int                g_pts[BB*NPTS];
__device__ unsigned int       g_okey[BB*NUM_OVER];
__device__ float              g_cflat[BB*NPTS*NCc];
__device__ float              g_flat[FINE_FLAT];
__device__ unsigned long long g_w1d[W1D_ULL];   // [k][o] = {w1[o][k], w1[o][k]}
__device__ unsigned long long g_w2d[W2D_ULL];   // [k][o] = {w2[o][k], w2[o][k]}

// ---------------- f32x2 helpers ----------------
__device__ __forceinline__ unsigned long long pk2(float lo, float hi) {
    unsigned long long r;
    asm("mov.b64 %0, {%1,%2};" : "=l"(r) : "f"(lo), "f"(hi));
    return r;
}
__device__ __forceinline__ void upk2(unsigned long long v, float& lo, float& hi) {
    asm("mov.b64 {%0,%1}, %2;" : "=f"(lo), "=f"(hi) : "l"(v));
}
__device__ __forceinline__ void fma2(unsigned long long& d, unsigned long long a,
                                     unsigned long long b) {
    asm("fma.rn.f32x2 %0, %1, %2, %0;" : "+l"(d) : "l"(a), "l"(b));
}

// =========================================================================
// k_unc: blocks 0..11 uncertainty keys (bit-identical); blocks 12.. repack
// DUPLICATED f32x2 weights, k-major: g_w1d[k*256+o] = {w1[o][k]}x2.
// =========================================================================
__global__ __launch_bounds__(1024) void k_unc(const float* __restrict__ coarse,
                                              const int* __restrict__ rnd,
                                              const float* __restrict__ w1,
                                              const float* __restrict__ w2) {
    if (blockIdx.x >= UNC_BLOCKS) {
        int t = (blockIdx.x - UNC_BLOCKS) * 1024 + threadIdx.x;
        if (t < W1D_ULL) {
            int k = t >> 8, o = t & 255;
            float v = (k < FEAT_DIM) ? w1[o*FEAT_DIM + k] : 0.f;
            g_w1d[t] = pk2(v, v);
        } else {
            int t2 = t - W1D_ULL;
            if (t2 < W2D_ULL) {
                int k = t2 >> 7, o = t2 & 127;
                float v = (k < FEAT_DIM) ? w2[o*FEAT_DIM + k] : 0.f;
                g_w2d[t2] = pk2(v, v);
            }
        }
        return;
    }
    int t = blockIdx.x * 1024 + threadIdx.x;
    int b = t / NUM_OVER, j = t - b * NUM_OVER;
    int idx = rnd[j];
    int h = idx / WW, w = idx % WW;
    float yc = (float)h * 0.25f - 0.375f;
    float xc = (float)w * 0.25f - 0.375f;
    int y0 = (int)floorf(yc); float fy = yc - (float)y0;
    int x0 = (int)floorf(xc); float fx = xc - (float)x0;
    int y0c = min(max(y0,   0), CHW-1), y1c = min(max(y0+1, 0), CHW-1);
    int x0c = min(max(x0,   0), CHW-1), x1c = min(max(x0+1, 0), CHW-1);
    float p[3];
    const float* base = coarse + (size_t)b * NCc * CHW * CHW;
#pragma unroll
    for (int c = 0; c < 3; c++) {
        const float* pc = base + c * CHW * CHW;
        float v00 = pc[y0c*CHW + x0c], v01 = pc[y0c*CHW + x1c];
        float v10 = pc[y1c*CHW + x0c], v11 = pc[y1c*CHW + x1c];
        float top = v00 * (1.f - fx) + v01 * fx;
        float bot = v10 * (1.f - fx) + v11 * fx;
        p[c] = top * (1.f - fy) + bot * fy;
    }
    float m  = fmaxf(p[0], fmaxf(p[1], p[2]));
    float e0 = expf(p[0]-m), e1 = expf(p[1]-m), e2 = expf(p[2]-m);
    float s  = e0 + e1 + e2;
    float q0 = e0/s, q1 = e1/s, q2 = e2/s;
    float mx  = fmaxf(q0, fmaxf(q1, q2));
    float mn  = fminf(q0, fminf(q1, q2));
    float mid = q0 + q1 + q2 - mx - mn;
    float u = 1.0f - (mx - mid);
    unsigned int bits = __float_as_uint(u);
    g_okey[t] = bits ^ ((bits >> 31) ? 0xFFFFFFFFu : 0x80000000u);
}

// =========================================================================
// k_sel (unchanged): 2 blocks, radix threshold + bitmap + ordered emit.
// =========================================================================
__global__ __launch_bounds__(1024) void k_sel(const int* __restrict__ rnd,
                                              float* __restrict__ mask_out) {
    extern __shared__ unsigned int dyn[];
    __shared__ int hist[256];
    __shared__ int sfxsum[257];
    __shared__ int warp_tot[32];
    __shared__ unsigned int s_prefix;
    __shared__ int s_need;

    int b = blockIdx.x;
    int tid = threadIdx.x;
    int lane = tid & 31, wrp = tid >> 5;

    for (int j = tid; j < NUM_OVER; j += 1024)
        dyn[j] = g_okey[b*NUM_OVER + j];
    if (tid == 0) { s_prefix = 0u; s_need = STEP1; }
    __syncthreads();

    for (int lvl = 0; lvl < 4; lvl++) {
        int shift = 24 - 8*lvl;
        unsigned int hi_mask = lvl ? (0xFFFFFFFFu << (shift + 8)) : 0u;
        unsigned int pref = s_prefix;
        int need = s_need;
        if (tid < 256) hist[tid] = 0;
        __syncthreads();
#pragma unroll
        for (int jj = 0; jj < CHUNK; jj++) {
            unsigned int ok = dyn[tid*CHUNK + jj];
            if ((ok & hi_mask) == pref) atomicAdd(&hist[(ok >> shift) & 255], 1);
        }
        __syncthreads();
        int x = (tid < 256) ? hist[255 - tid] : 0;
#pragma unroll
        for (int o = 1; o < 32; o <<= 1) {
            int y = __shfl_up_sync(0xFFFFFFFFu, x, o);
            if (lane >= o) x += y;
        }
        if (tid < 256 && lane == 31) warp_tot[wrp] = x;
        __syncthreads();
        if (tid < 256) {
            int basew = 0;
            for (int wq = 0; wq < wrp; wq++) basew += warp_tot[wq];
            sfxsum[255 - tid] = x + basew;
        }
        __syncthreads();
        if (tid < 256) {
            int S  = sfxsum[tid];
            int S1 = (tid == 255) ? 0 : sfxsum[tid + 1];
            if (S >= need && S1 < need) {
                s_prefix = pref | ((unsigned int)tid << shift);
                s_need = need - S1;
            }
        }
        __syncthreads();
    }
    unsigned int T = s_prefix;
    int need = s_need;

    unsigned int okv[CHUNK];
    int localeq = 0;
#pragma unroll
    for (int jj = 0; jj < CHUNK; jj++) {
        okv[jj] = dyn[tid*CHUNK + jj];
        localeq += (okv[jj] == T);
    }
    {
        int x = localeq;
#pragma unroll
        for (int o = 1; o < 32; o <<= 1) {
            int y = __shfl_up_sync(0xFFFFFFFFu, x, o);
            if (lane >= o) x += y;
        }
        if (lane == 31) warp_tot[wrp] = x;
        __syncthreads();
        int basew = 0;
        for (int wq = 0; wq < wrp; wq++) basew += warp_tot[wq];
        int rank = basew + x - localeq;
        unsigned int selmask = 0;
#pragma unroll
        for (int jj = 0; jj < CHUNK; jj++) {
            bool sel = okv[jj] > T;
            if (okv[jj] == T) { sel = (rank < need); rank++; }
            if (sel) selmask |= 1u << jj;
        }
        __syncthreads();
        for (int w = tid; w < NWORDS; w += 1024) dyn[w] = 0u;
        __syncthreads();
#pragma unroll
        for (int jj = 0; jj < CHUNK; jj++)
            if ((selmask >> jj) & 1u) {
                int lin = rnd[tid*CHUNK + jj];
                atomicOr(&dyn[lin >> 5], 1u << (lin & 31));
            }
    }
    for (int i = tid; i < STEP2; i += 1024) {
        int lin = rnd[HH*WW - STEP2 + i];
        atomicOr(&dyn[lin >> 5], 1u << (lin & 31));
    }
    __syncthreads();

    {
        int w0 = tid * 8;
        unsigned int words[8];
        int cnt = 0;
#pragma unroll
        for (int q = 0; q < 8; q++) { words[q] = dyn[w0 + q]; cnt += __popc(words[q]); }
        int incl = cnt;
#pragma unroll
        for (int o = 1; o < 32; o <<= 1) {
            int v = __shfl_up_sync(0xFFFFFFFFu, incl, o);
            if (lane >= o) incl += v;
        }
        if (lane == 31) warp_tot[wrp] = incl;
        __syncthreads();
        int basew = 0;
        for (int wq = 0; wq < wrp; wq++) basew += warp_tot[wq];
        int offset = basew + incl - cnt;
#pragma unroll
        for (int q = 0; q < 8; q++) {
            unsigned int m = words[q];
            int linbase = (w0 + q) * 32;
            while (m) {
                int bpos = __ffs(m) - 1; m &= m - 1;
                int lin = linbase + bpos;
                g_pts[b*NPTS + offset] = lin;
                mask_out[b*HH*WW + lin] = 1.0f;
                offset++;
            }
        }
    }
}

// =========================================================================
// k_sample (unchanged): one block per point, 256 threads = channels.
// =========================================================================
__global__ __launch_bounds__(256) void k_sample(const float* __restrict__ fine,
                                                const float* __restrict__ coarse) {
    int g = blockIdx.x;
    int b = g >> 11;
    int ch = threadIdx.x;
    int idx = g_pts[g];
    int h = idx >> 9, w = idx & 511;
    float yf = (float)h * 0.5f - 0.25f;
    float xf = (float)w * 0.5f - 0.25f;
    int y0 = (int)floorf(yf); float sfy = yf - (float)y0;
    int x0 = (int)floorf(xf); float sfx = xf - (float)x0;
    int sy0 = min(max(y0,   0), FHW-1), sy1 = min(max(y0+1, 0), FHW-1);
    int sx0 = min(max(x0,   0), FHW-1), sx1 = min(max(x0+1, 0), FHW-1);
    const float* pf = fine + ((size_t)b * CF + ch) * (FHW * FHW);
    float v00, v01, v10, v11;
    if ((sx1 == sx0 + 1) && ((sx0 & 1) == 0)) {
        float2 aa = *(const float2*)(pf + sy0*FHW + sx0);
        float2 dd = *(const float2*)(pf + sy1*FHW + sx0);
        v00 = aa.x; v01 = aa.y; v10 = dd.x; v11 = dd.y;
    } else {
        v00 = pf[sy0*FHW + sx0]; v01 = pf[sy0*FHW + sx1];
        v10 = pf[sy1*FHW + sx0]; v11 = pf[sy1*FHW + sx1];
    }
    float top = v00 * (1.f - sfx) + v01 * sfx;
    float bot = v10 * (1.f - sfx) + v11 * sfx;
    g_flat[(size_t)g * CF + ch] = top * (1.f - sfy) + bot * sfy;

    if (ch < NCc) {
        float yc = (float)h * 0.25f - 0.375f;
        float xc = (float)w * 0.25f - 0.375f;
        int cy = (int)floorf(yc); float cfy = yc - (float)cy;
        int cx = (int)floorf(xc); float cfx = xc - (float)cx;
        int cy0 = min(max(cy,   0), CHW-1), cy1 = min(max(cy+1, 0), CHW-1);
        int cx0 = min(max(cx,   0), CHW-1), cx1 = min(max(cx+1, 0), CHW-1);
        const float* pc = coarse + ((size_t)b * NCc + ch) * (CHW * CHW);
        float c00 = pc[cy0*CHW + cx0], c01 = pc[cy0*CHW + cx1];
        float c10 = pc[cy1*CHW + cx0], c11 = pc[cy1*CHW + cx1];
        float ctop = c00 * (1.f - cfx) + c01 * cfx;
        float cbot = c10 * (1.f - cfx) + c11 * cfx;
        g_cflat[g*NCc + ch] = ctop * (1.f - cfy) + cbot * cfy;
    }
}

// =========================================================================
// k_mlp: register-tiled GEMM. 128 blocks (1 wave), 256 threads, 32 rows.
// Layer1: thread = (ot 0..31, pt 0..7) computes outputs ot*8..+7 for pairs
//   2pt,2pt+1 -> 16 fma2 accumulators. Per k: 4 LDG.128 (dup weights,
//   L1-shared) + 2 broadcast LDS.64 + 16 fma2. k ascending -> bit-identical.
// Layer2: thread = (ot2 0..15, pt2 0..15), 8 accs, same pattern.
// =========================================================================
__global__ __launch_bounds__(256) void k_mlp(const float* __restrict__ w3,
                                             const float* __restrict__ pa,
                                             float* __restrict__ out) {
    extern __shared__ float sm[];
    float* xs  = sm;                         // 16 pairs x 260 x2  (8320)
    float* l1p = xs + NPR*FEAT_PAD*2;        // 16 pairs x 260 x2  (8320)
    float* l2s = l1p + NPR*FEAT_PAD*2;       // 32 x 128           (4096)
    float* w3s = l2s + RPB*128;              // 400

    int tid = threadIdx.x;
    int g0 = blockIdx.x * RPB;
    float a = *pa;

    // ---- load rows (coalesced) into pair-packed tile ----
    for (int q = tid; q < RPB*FEAT_PAD; q += 256) {
        int r = q / FEAT_PAD, c = q - r*FEAT_PAD;
        float v = 0.f;
        if (c < FEAT_DIM) {
            int f = (g0 + r) * FEAT_DIM + c;
            v = (f < FINE_FLAT) ? g_flat[f] : g_cflat[f - FINE_FLAT];
        }
        int pi = ((r >> 1) * FEAT_PAD + c) * 2 + (r & 1);
        xs[pi] = v;
        if (c >= 256) l1p[pi] = v;           // tail (+ zero pad) feeds layer 2
    }
    for (int q = tid; q < NCc*131; q += 256) w3s[q] = w3[q];
    __syncthreads();

    const unsigned long long* xsu  = (const unsigned long long*)xs;
    unsigned long long*       l1u  = (unsigned long long*)l1p;

    // ---- layer 1: 259 -> 256 ----
    {
        int ot = tid & 31;                   // outputs ot*8 .. ot*8+7
        int pt = tid >> 5;                   // pairs 2pt, 2pt+1
        int p0 = 2*pt, p1 = 2*pt + 1;
        unsigned long long acc[8][2];
#pragma unroll
        for (int ko = 0; ko < 8; ko++) { acc[ko][0] = 0ull; acc[ko][1] = 0ull; }

        for (int k = 0; k < FEAT_PAD; k += 2) {
            const ulonglong2* wk0 = (const ulonglong2*)(g_w1d + (size_t)k*256 + ot*8);
            const ulonglong2* wk1 = (const ulonglong2*)(g_w1d + (size_t)(k+1)*256 + ot*8);
            ulonglong2 wa0 = wk0[0], wa1 = wk0[1], wa2 = wk0[2], wa3 = wk0[3];
            ulonglong2 wb0 = wk1[0], wb1 = wk1[1], wb2 = wk1[2], wb3 = wk1[3];
            unsigned long long f00 = xsu[p0*FEAT_PAD + k];
            unsigned long long f01 = xsu[p1*FEAT_PAD + k];
            unsigned long long f10 = xsu[p0*FEAT_PAD + k + 1];
            unsigned long long f11 = xsu[p1*FEAT_PAD + k + 1];
            // k
            fma2(acc[0][0], wa0.x, f00); fma2(acc[0][1], wa0.x, f01);
            fma2(acc[1][0], wa0.y, f00); fma2(acc[1][1], wa0.y, f01);
            fma2(acc[2][0], wa1.x, f00); fma2(acc[2][1], wa1.x, f01);
            fma2(acc[3][0], wa1.y, f00); fma2(acc[3][1], wa1.y, f01);
            fma2(acc[4][0], wa2.x, f00); fma2(acc[4][1], wa2.x, f01);
            fma2(acc[5][0], wa2.y, f00); fma2(acc[5][1], wa2.y, f01);
            fma2(acc[6][0], wa3.x, f00); fma2(acc[6][1], wa3.x, f01);
            fma2(acc[7][0], wa3.y, f00); fma2(acc[7][1], wa3.y, f01);
            // k+1
            fma2(acc[0][0], wb0.x, f10); fma2(acc[0][1], wb0.x, f11);
            fma2(acc[1][0], wb0.y, f10); fma2(acc[1][1], wb0.y, f11);
            fma2(acc[2][0], wb1.x, f10); fma2(acc[2][1], wb1.x, f11);
            fma2(acc[3][0], wb1.y, f10); fma2(acc[3][1], wb1.y, f11);
            fma2(acc[4][0], wb2.x, f10); fma2(acc[4][1], wb2.x, f11);
            fma2(acc[5][0], wb2.y, f10); fma2(acc[5][1], wb2.y, f11);
            fma2(acc[6][0], wb3.x, f10); fma2(acc[6][1], wb3.x, f11);
            fma2(acc[7][0], wb3.y, f10); fma2(acc[7][1], wb3.y, f11);
        }
#pragma unroll
        for (int ko = 0; ko < 8; ko++) {
            int o = ot*8 + ko;
            float lo, hi;
            upk2(acc[ko][0], lo, hi);
            lo = lo >= 0.f ? lo : a*lo; hi = hi >= 0.f ? hi : a*hi;
            l1u[p0*FEAT_PAD + o] = pk2(lo, hi);
            upk2(acc[ko][1], lo, hi);
            lo = lo >= 0.f ? lo : a*lo; hi = hi >= 0.f ? hi : a*hi;
            l1u[p1*FEAT_PAD + o] = pk2(lo, hi);
        }
    }
    __syncthreads();

    // ---- layer 2: 259 -> 128 ----
    {
        int ot2 = tid & 15;                  // outputs ot2*8 .. ot2*8+7
        int pt2 = tid >> 4;                  // pair 0..15
        unsigned long long acc[8];
#pragma unroll
        for (int ko = 0; ko < 8; ko++) acc[ko] = 0ull;

        for (int k = 0; k < FEAT_PAD; k += 2) {
            const ulonglong2* wk0 = (const ulonglong2*)(g_w2d + (size_t)k*128 + ot2*8);
            const ulonglong2* wk1 = (const ulonglong2*)(g_w2d + (size_t)(k+1)*128 + ot2*8);
            ulonglong2 wa0 = wk0[0], wa1 = wk0[1], wa2 = wk0[2], wa3 = wk0[3];
            ulonglong2 wb0 = wk1[0], wb1 = wk1[1], wb2 = wk1[2], wb3 = wk1[3];
            unsigned long long f0 = l1u[pt2*FEAT_PAD + k];
            unsigned long long f1 = l1u[pt2*FEAT_PAD + k + 1];
            fma2(acc[0], wa0.x, f0); fma2(acc[1], wa0.y, f0);
            fma2(acc[2], wa1.x, f0); fma2(acc[3], wa1.y, f0);
            fma2(acc[4], wa2.x, f0); fma2(acc[5], wa2.y, f0);
            fma2(acc[6], wa3.x, f0); fma2(acc[7], wa3.y, f0);
            fma2(acc[0], wb0.x, f1); fma2(acc[1], wb0.y, f1);
            fma2(acc[2], wb1.x, f1); fma2(acc[3], wb1.y, f1);
            fma2(acc[4], wb2.x, f1); fma2(acc[5], wb2.y, f1);
            fma2(acc[6], wb3.x, f1); fma2(acc[7], wb3.y, f1);
        }
#pragma unroll
        for (int ko = 0; ko < 8; ko++) {
            int o = ot2*8 + ko;
            float lo, hi; upk2(acc[ko], lo, hi);
            lo = lo >= 0.f ? lo : a*lo; hi = hi >= 0.f ? hi : a*hi;
            l2s[(2*pt2    )*128 + o] = lo;
            l2s[(2*pt2 + 1)*128 + o] = hi;
        }
    }
    __syncthreads();

    // ---- layer 3: 131 -> 3 ----
    if (tid < RPB*NCc) {
        int r = tid / 3, oo = tid % 3;
        float s = 0.f;
        for (int c = 0; c < 128; c++) s = fmaf(w3s[oo*131 + c], l2s[r*128 + c], s);
#pragma unroll
        for (int q = 0; q < 3; q++) {
            float xt = xs[((r >> 1)*FEAT_PAD + 256 + q)*2 + (r & 1)];
            s = fmaf(w3s[oo*131 + 128 + q], xt, s);
        }
        int g = g0 + r;
        int b = g >> 11, n = g & 2047;
        out[(b*NCc + oo)*NPTS + n] = s;
    }
}

// ---------------- launch ----------------
extern "C" void kernel_launch(void* const* d_in, const int* in_sizes, int n_in,
                              void* d_out, int out_size) {
    const float* fine   = (const float*)d_in[0];
    const float* coarse = (const float*)d_in[1];
    const float* w1     = (const float*)d_in[2];
    const float* w2     = (const float*)d_in[3];
    const float* w3     = (const float*)d_in[4];
    const float* pa     = (const float*)d_in[5];
    const int*   rnd    = (const int*)d_in[6];
    float* out = (float*)d_out;

    static int configured = 0;
    int mlp_smem = (2*NPR*FEAT_PAD*2 + RPB*128 + 400) * (int)sizeof(float);
    if (!configured) {
        cudaFuncSetAttribute(k_sel, cudaFuncAttributeMaxDynamicSharedMemorySize,
                             NWORDS * (int)sizeof(unsigned int));
        cudaFuncSetAttribute(k_mlp, cudaFuncAttributeMaxDynamicSharedMemorySize,
                             mlp_smem);
        configured = 1;
    }

    cudaMemsetAsync(out + OUT_OFF, 0, (size_t)MASK_SIZE * sizeof(float), 0);
    k_unc<<<UNC_BLOCKS + REPACK_BLOCKS, 1024>>>(coarse, rnd, w1, w2);
    k_sel<<<BB, 1024, NWORDS * sizeof(unsigned int)>>>(rnd, out + OUT_OFF);
    k_sample<<<NROWS, 256>>>(fine, coarse);
    k_mlp<<<NROWS/RPB, 256, mlp_smem>>>(w3, pa, out);
    (void)in_sizes; (void)n_in; (void)out_size;
}

// round 16
// speedup vs baseline: 3.0249x; 3.0249x over previous
#include <cuda_runtime.h>
#include <math.h>

#define HH 512
#define WW 512
#define CHW 128
#define FHW 256
#define CF 256
#define NCc 3
#define NPTS 2048
#define NUM_OVER 6144
#define CHUNK 6
#define STEP1 1536
#define STEP2 512
#define BB 2
#define FEAT_DIM 259
#define FEAT_PAD 260
#define NCB1 65
#define NROWS (BB*NPTS)
#define FINE_FLAT (BB*NPTS*CF)
#define OUT_OFF (BB*NCc*NPTS)
#define MASK_SIZE (BB*HH*WW)
#define RPB 16
#define HPAIR 4
#define HTILE (HPAIR*FEAT_PAD*2)
#define NWORDS (HH*WW/32)
#define W1P_ELEMS (NCB1*256*4)
#define W2P_ELEMS (NCB1*128*4)
#define UNC_BLOCKS 12
#define REPACK_BLOCKS 98
#define CBC 5                                // cb per weight chunk
#define NCHK 13                              // 13*5 = 65 chunks
#define W1CHK (CBC*256*4)                    // 5120 floats per layer1 chunk
#define W2CHK (CBC*128*4)                    // 2560 floats per layer2 chunk

// ---------------- device scratch ----------------
__device__ int          g_pts[BB*NPTS];
__device__ unsigned int g_okey[BB*NUM_OVER];
__device__ float        g_cflat[BB*NPTS*NCc];
__device__ float        g_flat[FINE_FLAT];
__device__ float        g_w1p[W1P_ELEMS];
__device__ float        g_w2p[W2P_ELEMS];

// ---------------- f32x2 / cp.async helpers ----------------
__device__ __forceinline__ unsigned long long pk2(float lo, float hi) {
    unsigned long long r;
    asm("mov.b64 %0, {%1,%2};" : "=l"(r) : "f"(lo), "f"(hi));
    return r;
}
__device__ __forceinline__ void upk2(unsigned long long v, float& lo, float& hi) {
    asm("mov.b64 {%0,%1}, %2;" : "=f"(lo), "=f"(hi) : "l"(v));
}
__device__ __forceinline__ void fma2(unsigned long long& d, unsigned long long a,
                                     unsigned long long b) {
    asm("fma.rn.f32x2 %0, %1, %2, %0;" : "+l"(d) : "l"(a), "l"(b));
}
__device__ __forceinline__ void cpa16(unsigned int dst, const float* src) {
    asm volatile("cp.async.ca.shared.global [%0], [%1], 16;" :: "r"(dst), "l"(src));
}
#define CPA_COMMIT() asm volatile("cp.async.commit_group;" ::: "memory")
#define CPA_WAIT1()  asm volatile("cp.async.wait_group 1;" ::: "memory")
#define CPA_WAIT0()  asm volatile("cp.async.wait_group 0;" ::: "memory")

// =========================================================================
// k_unc (unchanged): blocks 0..11 uncertainty keys; blocks 12.. repack.
// =========================================================================
__global__ __launch_bounds__(1024) void k_unc(const float* __restrict__ coarse,
                                              const int* __restrict__ rnd,
                                              const float* __restrict__ w1,
                                              const float* __restrict__ w2) {
    if (blockIdx.x >= UNC_BLOCKS) {
        int t = (blockIdx.x - UNC_BLOCKS) * 1024 + threadIdx.x;
        if (t < W1P_ELEMS) {
            int cb = t >> 10, rest = t & 1023;
            int o = rest >> 2, q = rest & 3, c = cb * 4 + q;
            g_w1p[t] = (c < FEAT_DIM) ? w1[o*FEAT_DIM + c] : 0.f;
        } else {
            int t2 = t - W1P_ELEMS;
            if (t2 < W2P_ELEMS) {
                int cb = t2 >> 9, rest = t2 & 511;
                int o = rest >> 2, q = rest & 3, c = cb * 4 + q;
                g_w2p[t2] = (c < FEAT_DIM) ? w2[o*FEAT_DIM + c] : 0.f;
            }
        }
        return;
    }
    int t = blockIdx.x * 1024 + threadIdx.x;
    int b = t / NUM_OVER, j = t - b * NUM_OVER;
    int idx = rnd[j];
    int h = idx / WW, w = idx % WW;
    float yc = (float)h * 0.25f - 0.375f;
    float xc = (float)w * 0.25f - 0.375f;
    int y0 = (int)floorf(yc); float fy = yc - (float)y0;
    int x0 = (int)floorf(xc); float fx = xc - (float)x0;
    int y0c = min(max(y0,   0), CHW-1), y1c = min(max(y0+1, 0), CHW-1);
    int x0c = min(max(x0,   0), CHW-1), x1c = min(max(x0+1, 0), CHW-1);
    float p[3];
    const float* base = coarse + (size_t)b * NCc * CHW * CHW;
#pragma unroll
    for (int c = 0; c < 3; c++) {
        const float* pc = base + c * CHW * CHW;
        float v00 = pc[y0c*CHW + x0c], v01 = pc[y0c*CHW + x1c];
        float v10 = pc[y1c*CHW + x0c], v11 = pc[y1c*CHW + x1c];
        float top = v00 * (1.f - fx) + v01 * fx;
        float bot = v10 * (1.f - fx) + v11 * fx;
        p[c] = top * (1.f - fy) + bot * fy;
    }
    float m  = fmaxf(p[0], fmaxf(p[1], p[2]));
    float e0 = expf(p[0]-m), e1 = expf(p[1]-m), e2 = expf(p[2]-m);
    float s  = e0 + e1 + e2;
    float q0 = e0/s, q1 = e1/s, q2 = e2/s;
    float mx  = fmaxf(q0, fmaxf(q1, q2));
    float mn  = fminf(q0, fminf(q1, q2));
    float mid = q0 + q1 + q2 - mx - mn;
    float u = 1.0f - (mx - mid);
    unsigned int bits = __float_as_uint(u);
    g_okey[t] = bits ^ ((bits >> 31) ? 0xFFFFFFFFu : 0x80000000u);
}

// =========================================================================
// k_sel (unchanged): 2 blocks, radix threshold + bitmap + ordered emit.
// =========================================================================
__global__ __launch_bounds__(1024) void k_sel(const int* __restrict__ rnd,
                                              float* __restrict__ mask_out) {
    extern __shared__ unsigned int dyn[];
    __shared__ int hist[256];
    __shared__ int sfxsum[257];
    __shared__ int warp_tot[32];
    __shared__ unsigned int s_prefix;
    __shared__ int s_need;

    int b = blockIdx.x;
    int tid = threadIdx.x;
    int lane = tid & 31, wrp = tid >> 5;

    for (int j = tid; j < NUM_OVER; j += 1024)
        dyn[j] = g_okey[b*NUM_OVER + j];
    if (tid == 0) { s_prefix = 0u; s_need = STEP1; }
    __syncthreads();

    for (int lvl = 0; lvl < 4; lvl++) {
        int shift = 24 - 8*lvl;
        unsigned int hi_mask = lvl ? (0xFFFFFFFFu << (shift + 8)) : 0u;
        unsigned int pref = s_prefix;
        int need = s_need;
        if (tid < 256) hist[tid] = 0;
        __syncthreads();
#pragma unroll
        for (int jj = 0; jj < CHUNK; jj++) {
            unsigned int ok = dyn[tid*CHUNK + jj];
            if ((ok & hi_mask) == pref) atomicAdd(&hist[(ok >> shift) & 255], 1);
        }
        __syncthreads();
        int x = (tid < 256) ? hist[255 - tid] : 0;
#pragma unroll
        for (int o = 1; o < 32; o <<= 1) {
            int y = __shfl_up_sync(0xFFFFFFFFu, x, o);
            if (lane >= o) x += y;
        }
        if (tid < 256 && lane == 31) warp_tot[wrp] = x;
        __syncthreads();
        if (tid < 256) {
            int basew = 0;
            for (int wq = 0; wq < wrp; wq++) basew += warp_tot[wq];
            sfxsum[255 - tid] = x + basew;
        }
        __syncthreads();
        if (tid < 256) {
            int S  = sfxsum[tid];
            int S1 = (tid == 255) ? 0 : sfxsum[tid + 1];
            if (S >= need && S1 < need) {
                s_prefix = pref | ((unsigned int)tid << shift);
                s_need = need - S1;
            }
        }
        __syncthreads();
    }
    unsigned int T = s_prefix;
    int need = s_need;

    unsigned int okv[CHUNK];
    int localeq = 0;
#pragma unroll
    for (int jj = 0; jj < CHUNK; jj++) {
        okv[jj] = dyn[tid*CHUNK + jj];
        localeq += (okv[jj] == T);
    }
    {
        int x = localeq;
#pragma unroll
        for (int o = 1; o < 32; o <<= 1) {
            int y = __shfl_up_sync(0xFFFFFFFFu, x, o);
            if (lane >= o) x += y;
        }
        if (lane == 31) warp_tot[wrp] = x;
        __syncthreads();
        int basew = 0;
        for (int wq = 0; wq < wrp; wq++) basew += warp_tot[wq];
        int rank = basew + x - localeq;
        unsigned int selmask = 0;
#pragma unroll
        for (int jj = 0; jj < CHUNK; jj++) {
            bool sel = okv[jj] > T;
            if (okv[jj] == T) { sel = (rank < need); rank++; }
            if (sel) selmask |= 1u << jj;
        }
        __syncthreads();
        for (int w = tid; w < NWORDS; w += 1024) dyn[w] = 0u;
        __syncthreads();
#pragma unroll
        for (int jj = 0; jj < CHUNK; jj++)
            if ((selmask >> jj) & 1u) {
                int lin = rnd[tid*CHUNK + jj];
                atomicOr(&dyn[lin >> 5], 1u << (lin & 31));
            }
    }
    for (int i = tid; i < STEP2; i += 1024) {
        int lin = rnd[HH*WW - STEP2 + i];
        atomicOr(&dyn[lin >> 5], 1u << (lin & 31));
    }
    __syncthreads();

    {
        int w0 = tid * 8;
        unsigned int words[8];
        int cnt = 0;
#pragma unroll
        for (int q = 0; q < 8; q++) { words[q] = dyn[w0 + q]; cnt += __popc(words[q]); }
        int incl = cnt;
#pragma unroll
        for (int o = 1; o < 32; o <<= 1) {
            int v = __shfl_up_sync(0xFFFFFFFFu, incl, o);
            if (lane >= o) incl += v;
        }
        if (lane == 31) warp_tot[wrp] = incl;
        __syncthreads();
        int basew = 0;
        for (int wq = 0; wq < wrp; wq++) basew += warp_tot[wq];
        int offset = basew + incl - cnt;
#pragma unroll
        for (int q = 0; q < 8; q++) {
            unsigned int m = words[q];
            int linbase = (w0 + q) * 32;
            while (m) {
                int bpos = __ffs(m) - 1; m &= m - 1;
                int lin = linbase + bpos;
                g_pts[b*NPTS + offset] = lin;
                mask_out[b*HH*WW + lin] = 1.0f;
                offset++;
            }
        }
    }
}

// =========================================================================
// k_sample (unchanged): one block per point, 256 threads = channels.
// =========================================================================
__global__ __launch_bounds__(256) void k_sample(const float* __restrict__ fine,
                                                const float* __restrict__ coarse) {
    int g = blockIdx.x;
    int b = g >> 11;
    int ch = threadIdx.x;
    int idx = g_pts[g];
    int h = idx >> 9, w = idx & 511;
    float yf = (float)h * 0.5f - 0.25f;
    float xf = (float)w * 0.5f - 0.25f;
    int y0 = (int)floorf(yf); float sfy = yf - (float)y0;
    int x0 = (int)floorf(xf); float sfx = xf - (float)x0;
    int sy0 = min(max(y0,   0), FHW-1), sy1 = min(max(y0+1, 0), FHW-1);
    int sx0 = min(max(x0,   0), FHW-1), sx1 = min(max(x0+1, 0), FHW-1);
    const float* pf = fine + ((size_t)b * CF + ch) * (FHW * FHW);
    float v00, v01, v10, v11;
    if ((sx1 == sx0 + 1) && ((sx0 & 1) == 0)) {
        float2 aa = *(const float2*)(pf + sy0*FHW + sx0);
        float2 dd = *(const float2*)(pf + sy1*FHW + sx0);
        v00 = aa.x; v01 = aa.y; v10 = dd.x; v11 = dd.y;
    } else {
        v00 = pf[sy0*FHW + sx0]; v01 = pf[sy0*FHW + sx1];
        v10 = pf[sy1*FHW + sx0]; v11 = pf[sy1*FHW + sx1];
    }
    float top = v00 * (1.f - sfx) + v01 * sfx;
    float bot = v10 * (1.f - sfx) + v11 * sfx;
    g_flat[(size_t)g * CF + ch] = top * (1.f - sfy) + bot * sfy;

    if (ch < NCc) {
        float yc = (float)h * 0.25f - 0.375f;
        float xc = (float)w * 0.25f - 0.375f;
        int cy = (int)floorf(yc); float cfy = yc - (float)cy;
        int cx = (int)floorf(xc); float cfx = xc - (float)cx;
        int cy0 = min(max(cy,   0), CHW-1), cy1 = min(max(cy+1, 0), CHW-1);
        int cx0 = min(max(cx,   0), CHW-1), cx1 = min(max(cx+1, 0), CHW-1);
        const float* pc = coarse + ((size_t)b * NCc + ch) * (CHW * CHW);
        float c00 = pc[cy0*CHW + cx0], c01 = pc[cy0*CHW + cx1];
        float c10 = pc[cy1*CHW + cx0], c11 = pc[cy1*CHW + cx1];
        float ctop = c00 * (1.f - cfx) + c01 * cfx;
        float cbot = c10 * (1.f - cfx) + c11 * cfx;
        g_cflat[g*NCc + ch] = ctop * (1.f - cfy) + cbot * cfy;
    }
}

// =========================================================================
// k_mlp: R13 structure (512 thr, two 8-row halves, 54us baseline) with
// weights staged gmem->smem via double-buffered cp.async (13 chunks x 5 cb).
// Weight LDG removed from the fma chain; accumulation order unchanged ->
// bit-identical output.
// =========================================================================
__global__ __launch_bounds__(512) void k_mlp(const float* __restrict__ w3,
                                             const float* __restrict__ pa,
                                             float* __restrict__ out) {
    extern __shared__ float sm[];
    float* xsp  = sm;                        // 2 x HTILE = 4160
    float* l1p  = xsp + 2*HTILE;             // 4160
    float* l2s  = l1p + 2*HTILE;             // 16 x 128 = 2048
    float* w3s  = l2s + RPB*128;             // 400
    float* wbuf = w3s + 400;                 // 2 x 5120

    int tid = threadIdx.x;
    int g0 = blockIdx.x * RPB;
    float a = *pa;
    int hf = tid >> 8;
    int t  = tid & 255;
    float* xh = xsp + hf*HTILE;
    float* lh = l1p + hf*HTILE;
    unsigned int wb = (unsigned int)__cvta_generic_to_shared(wbuf);

    // ---- prefetch layer1 chunk 0 (overlaps prologue) ----
    for (int ofs = tid*4; ofs < W1CHK; ofs += 2048)
        cpa16(wb + (unsigned int)ofs*4u, (const float*)g_w1p + ofs);
    CPA_COMMIT();

    // ---- load rows (coalesced) into per-half pair tiles ----
    for (int q = tid; q < RPB*FEAT_PAD; q += 512) {
        int r = q / FEAT_PAD, c = q - r*FEAT_PAD;
        float v = 0.f;
        if (c < FEAT_DIM) {
            int f = (g0 + r) * FEAT_DIM + c;
            v = (f < FINE_FLAT) ? g_flat[f] : g_cflat[f - FINE_FLAT];
        }
        int hh = r >> 3, rl = r & 7;
        int pi = hh*HTILE + ((rl >> 1) * FEAT_PAD + c) * 2 + (rl & 1);
        xsp[pi] = v;
        if (c >= 256) l1p[pi] = v;
    }
    for (int q = tid; q < NCc*131; q += 512) w3s[q] = w3[q];
    __syncthreads();

    // ---- layer 1: 259 -> 256, prelu (4 pairs/thread/half) ----
    {
        unsigned long long accp[HPAIR];
#pragma unroll
        for (int pr = 0; pr < HPAIR; pr++) accp[pr] = 0ull;

        for (int c = 0; c < NCHK; c++) {
            if (c + 1 < NCHK) {
                const float* src = (const float*)g_w1p + (c+1)*W1CHK;
                unsigned int dst = wb + (unsigned int)(((c+1)&1)*5120)*4u;
                for (int ofs = tid*4; ofs < W1CHK; ofs += 2048)
                    cpa16(dst + (unsigned int)ofs*4u, src + ofs);
                CPA_COMMIT();
                CPA_WAIT1();
            } else {
                CPA_WAIT0();
            }
            __syncthreads();                 // chunk c ready for all threads
            const float4* wchunk = (const float4*)(wbuf + (c&1)*5120);
#pragma unroll
            for (int cl = 0; cl < CBC; cl++) {
                int cb = c*CBC + cl;
                float4 wv = wchunk[cl*256 + t];
                unsigned long long wp0 = pk2(wv.x, wv.x), wp1 = pk2(wv.y, wv.y);
                unsigned long long wp2 = pk2(wv.z, wv.z), wp3 = pk2(wv.w, wv.w);
#pragma unroll
                for (int pr = 0; pr < HPAIR; pr++) {
                    const ulonglong2* xp =
                        (const ulonglong2*)&xh[(pr*FEAT_PAD + cb*4) * 2];
                    ulonglong2 u0 = xp[0], u1 = xp[1];
                    fma2(accp[pr], wp0, u0.x);
                    fma2(accp[pr], wp1, u0.y);
                    fma2(accp[pr], wp2, u1.x);
                    fma2(accp[pr], wp3, u1.y);
                }
            }
            __syncthreads();                 // compute done before buffer reuse
        }
#pragma unroll
        for (int pr = 0; pr < HPAIR; pr++) {
            float lo, hi; upk2(accp[pr], lo, hi);
            lo = lo >= 0.f ? lo : a * lo;
            hi = hi >= 0.f ? hi : a * hi;
            ((float2*)lh)[pr*FEAT_PAD + t] = make_float2(lo, hi);
        }
    }
    // ---- prefetch layer2 chunk 0 ----
    for (int ofs = tid*4; ofs < W2CHK; ofs += 2048)
        cpa16(wb + (unsigned int)ofs*4u, (const float*)g_w2p + ofs);
    CPA_COMMIT();
    __syncthreads();                         // l1p visible + chunk0 in flight

    // ---- layer 2: 259 -> 128, prelu (2 pairs/thread/half) ----
    {
        int o2 = t & 127;
        int rh = t >> 7;
        unsigned long long acc2[2];
        acc2[0] = 0ull; acc2[1] = 0ull;

        for (int c = 0; c < NCHK; c++) {
            if (c + 1 < NCHK) {
                const float* src = (const float*)g_w2p + (c+1)*W2CHK;
                unsigned int dst = wb + (unsigned int)(((c+1)&1)*5120)*4u;
                for (int ofs = tid*4; ofs < W2CHK; ofs += 2048)
                    cpa16(dst + (unsigned int)ofs*4u, src + ofs);
                CPA_COMMIT();
                CPA_WAIT1();
            } else {
                CPA_WAIT0();
            }
            __syncthreads();
            const float4* wchunk = (const float4*)(wbuf + (c&1)*5120);
#pragma unroll
            for (int cl = 0; cl < CBC; cl++) {
                int cb = c*CBC + cl;
                float4 wv = wchunk[cl*128 + o2];
                unsigned long long wp0 = pk2(wv.x, wv.x), wp1 = pk2(wv.y, wv.y);
                unsigned long long wp2 = pk2(wv.z, wv.z), wp3 = pk2(wv.w, wv.w);
#pragma unroll
                for (int pp = 0; pp < 2; pp++) {
                    int pr = rh*2 + pp;
                    const ulonglong2* xp =
                        (const ulonglong2*)&lh[(pr*FEAT_PAD + cb*4) * 2];
                    ulonglong2 u0 = xp[0], u1 = xp[1];
                    fma2(acc2[pp], wp0, u0.x);
                    fma2(acc2[pp], wp1, u0.y);
                    fma2(acc2[pp], wp2, u1.x);
                    fma2(acc2[pp], wp3, u1.y);
                }
            }
            __syncthreads();
        }
#pragma unroll
        for (int pp = 0; pp < 2; pp++) {
            int pr = rh*2 + pp;
            float lo, hi; upk2(acc2[pp], lo, hi);
            lo = lo >= 0.f ? lo : a * lo;
            hi = hi >= 0.f ? hi : a * hi;
            l2s[hf*1024 + (2*pr  )*128 + o2] = lo;
            l2s[hf*1024 + (2*pr+1)*128 + o2] = hi;
        }
    }
    __syncthreads();

    // ---- layer 3: 131 -> 3 ----
    if (t < 8*NCc) {
        int r = t / 3, oo = t % 3;
        float s = 0.f;
        for (int c = 0; c < 128; c++)
            s = fmaf(w3s[oo*131 + c], l2s[hf*1024 + r*128 + c], s);
#pragma unroll
        for (int q = 0; q < 3; q++) {
            float xt = xh[((r >> 1)*FEAT_PAD + 256 + q)*2 + (r & 1)];
            s = fmaf(w3s[oo*131 + 128 + q], xt, s);
        }
        int g = g0 + hf*8 + r;
        int b = g >> 11, n = g & 2047;
        out[(b*NCc + oo)*NPTS + n] = s;
    }
}

// ---------------- launch ----------------
extern "C" void kernel_launch(void* const* d_in, const int* in_sizes, int n_in,
                              void* d_out, int out_size) {
    const float* fine   = (const float*)d_in[0];
    const float* coarse = (const float*)d_in[1];
    const float* w1     = (const float*)d_in[2];
    const float* w2     = (const float*)d_in[3];
    const float* w3     = (const float*)d_in[4];
    const float* pa     = (const float*)d_in[5];
    const int*   rnd    = (const int*)d_in[6];
    float* out = (float*)d_out;

    static int configured = 0;
    int mlp_smem = (2*HTILE*2 + RPB*128 + 400 + 2*5120) * (int)sizeof(float);
    if (!configured) {
        cudaFuncSetAttribute(k_sel, cudaFuncAttributeMaxDynamicSharedMemorySize,
                             NWORDS * (int)sizeof(unsigned int));
        cudaFuncSetAttribute(k_mlp, cudaFuncAttributeMaxDynamicSharedMemorySize,
                             mlp_smem);
        configured = 1;
    }

    cudaMemsetAsync(out + OUT_OFF, 0, (size_t)MASK_SIZE * sizeof(float), 0);
    k_unc<<<UNC_BLOCKS + REPACK_BLOCKS, 1024>>>(coarse, rnd, w1, w2);
    k_sel<<<BB, 1024, NWORDS * sizeof(unsigned int)>>>(rnd, out + OUT_OFF);
    k_sample<<<NROWS, 256>>>(fine, coarse);
    k_mlp<<<NROWS/RPB, 512, mlp_smem>>>(w3, pa, out);
    (void)in_sizes; (void)n_in; (void)out_size;
}